// round 7
// baseline (speedup 1.0000x reference)
#include <cuda_runtime.h>
#include <math.h>

#define NN 100000
#define EE 1600000
#define DD 128
#define HID 32

typedef unsigned long long ull;

// ---------------- scratch (device globals) ------------------------------------
__device__ int      g_is64;
__device__ int      g_deg[NN];
__device__ float    g_dinv[NN];
__device__ int      g_off[NN + 1];
__device__ int      g_cur[NN];
__device__ int      g_src32[EE];
__device__ int      g_dst32[EE];
__device__ int      g_srcs[EE];             // CSR src ids (dst-bucketed)
__device__ ull      g_y2[(size_t)NN * 32];  // (z,h) packed per (node,lane); scaled by dinv
__device__ float    g_H[(size_t)NN * HID];
__device__ float    g_WT[64 * DD];          // WeffT[j][k], j: 0..31=z, 32..63=h
__device__ ull      g_beff2[32];            // packed (bz_eff, bh_eff)
__device__ unsigned g_part[128];            // decoupled-lookback partials (flagged)
__device__ int      g_done;                 // grid-barrier arrival counter

// ---------------- f32x2 helpers -----------------------------------------------
__device__ __forceinline__ ull pack2(float a, float b) {
    ull r; asm("mov.b64 %0, {%1, %2};" : "=l"(r) : "f"(a), "f"(b)); return r;
}
__device__ __forceinline__ void unpack2(ull v, float& a, float& b) {
    asm("mov.b64 {%0, %1}, %2;" : "=f"(a), "=f"(b) : "l"(v));
}
__device__ __forceinline__ ull fma2(ull a, ull b, ull c) {
    ull d; asm("fma.rn.f32x2 %0, %1, %2, %3;" : "=l"(d) : "l"(a), "l"(b), "l"(c)); return d;
}
__device__ __forceinline__ ull mul2(ull a, ull b) {
    ull d; asm("mul.rn.f32x2 %0, %1, %2;" : "=l"(d) : "l"(a), "l"(b)); return d;
}
__device__ __forceinline__ ull add2(ull a, ull b) {
    ull d; asm("add.rn.f32x2 %0, %1, %2;" : "=l"(d) : "l"(a), "l"(b)); return d;
}

__device__ __forceinline__ int edge_at(const void* ei, int is64, long long idx) {
    return is64 ? (int)((const long long*)ei)[idx] : ((const int*)ei)[idx];
}

// ---------------- prep: detect + deg init + sync-state reset + Weff^T ---------
__global__ void k_prep(const void* ei,
                       const float* Wz, const float* Wh,
                       const float* Lzw, const float* Lhw,
                       const float* bz, const float* bh,
                       const float* Lzb, const float* Lhb) {
    int b = blockIdx.x, t = threadIdx.x;
    if (b < 391) {
        int i = b * 256 + t;
        if (i < NN) g_deg[i] = 1;           // self loop
    } else if (b == 391) {
        __shared__ int s;
        if (t == 0) s = 1;
        __syncthreads();
        const long long* p = (const long long*)ei;
        for (int i = t; i < 4096; i += 256)
            if ((p[i] >> 32) != 0) s = 0;
        __syncthreads();
        if (t == 0) g_is64 = s;
        if (t < 128) g_part[t] = 0;         // reset lookback state (graph replay!)
        if (t == 128) g_done = 0;           // reset grid barrier
    } else {
        int idx = (b - 392) * 256 + t;      // [0, 8192)
        int k = idx >> 6, j = idx & 63;
        float acc = 0.f;
        if (j < HID) {
            for (int m = 0; m < HID; m++) acc = fmaf(Wz[k * HID + m], Lzw[m * HID + j], acc);
        } else {
            int jj = j - HID;
            for (int m = 0; m < HID; m++) acc = fmaf(Wh[k * HID + m], Lhw[m * HID + jj], acc);
        }
        g_WT[j * DD + k] = acc;             // transposed store
        if (b == 392 && t < 32) {
            float az = Lzb[t], ah = Lhb[t];
            for (int m = 0; m < HID; m++) {
                az = fmaf(bz[m], Lzw[m * HID + t], az);
                ah = fmaf(bh[m], Lhw[m * HID + t], ah);
            }
            g_beff2[t] = pack2(az, ah);
        }
    }
}

// ---------------- fused: GEMM (blocks [0,GEMMB)) + edge conv/degree ----------
#define GEMMB 3125
#define DEGB  6250
__global__ void k_main1(const float* __restrict__ x, const void* __restrict__ ei) {
    __shared__ float sWT[64 * 130];         // padded rows: stride 130 floats
    int t = threadIdx.x;
    if (blockIdx.x < GEMMB) {
        for (int i = t; i < 64 * 128; i += 256) {
            int j = i >> 7, k = i & 127;
            sWT[j * 130 + k] = g_WT[i];
        }
        __syncthreads();
        int warp = t >> 5, lane = t & 31;
        int n0 = (blockIdx.x * 8 + warp) * 4;       // 4 nodes per warp
        if (n0 >= NN) return;
        const float4* x4 = (const float4*)x;
        ull az[4] = {0, 0, 0, 0}, ah[4] = {0, 0, 0, 0};
        const ull* wzr = (const ull*)&sWT[lane * 130];
        const ull* whr = (const ull*)&sWT[(lane + 32) * 130];
#pragma unroll 4
        for (int k4 = 0; k4 < 32; k4++) {
            float4 a0 = x4[(size_t)(n0 + 0) * 32 + k4];
            float4 a1 = x4[(size_t)(n0 + 1) * 32 + k4];
            float4 a2 = x4[(size_t)(n0 + 2) * 32 + k4];
            float4 a3 = x4[(size_t)(n0 + 3) * 32 + k4];
            ull wz0 = wzr[k4 * 2], wz1 = wzr[k4 * 2 + 1];
            ull wh0 = whr[k4 * 2], wh1 = whr[k4 * 2 + 1];
            const ull* p0 = (const ull*)&a0; const ull* p1 = (const ull*)&a1;
            const ull* p2 = (const ull*)&a2; const ull* p3 = (const ull*)&a3;
            az[0] = fma2(p0[0], wz0, az[0]); az[0] = fma2(p0[1], wz1, az[0]);
            ah[0] = fma2(p0[0], wh0, ah[0]); ah[0] = fma2(p0[1], wh1, ah[0]);
            az[1] = fma2(p1[0], wz0, az[1]); az[1] = fma2(p1[1], wz1, az[1]);
            ah[1] = fma2(p1[0], wh0, ah[1]); ah[1] = fma2(p1[1], wh1, ah[1]);
            az[2] = fma2(p2[0], wz0, az[2]); az[2] = fma2(p2[1], wz1, az[2]);
            ah[2] = fma2(p2[0], wh0, ah[2]); ah[2] = fma2(p2[1], wh1, ah[2]);
            az[3] = fma2(p3[0], wz0, az[3]); az[3] = fma2(p3[1], wz1, az[3]);
            ah[3] = fma2(p3[0], wh0, ah[3]); ah[3] = fma2(p3[1], wh1, ah[3]);
        }
#pragma unroll
        for (int i = 0; i < 4; i++) {
            float zl, zh, hl, hh;
            unpack2(az[i], zl, zh);
            unpack2(ah[i], hl, hh);
            g_y2[(size_t)(n0 + i) * 32 + lane] = pack2(zl + zh, hl + hh);
        }
    } else {
        int is64 = g_is64;
        int e = (blockIdx.x - GEMMB) * 256 + t;
        if (e < EE) {
            int s = edge_at(ei, is64, e);
            int d = edge_at(ei, is64, (long long)EE + e);
            g_src32[e] = s;
            g_dst32[e] = d;
            atomicAdd(&g_deg[d], 1);
        }
    }
}

// ---------------- one-wave: scan (decoupled lookback) + scale + scatter -------
#define SB 98
__global__ void __launch_bounds__(1024, 1) k_scanscat() {
    __shared__ int warpsums[32];
    __shared__ unsigned spart[128];
    __shared__ int sprefix;
    int b = blockIdx.x, t = threadIdx.x, lane = t & 31, w = t >> 5;

    // --- phase A: local exclusive scan of (deg-1), dinv ---
    int i = b * 1024 + t;
    int dg = (i < NN) ? g_deg[i] : 1;
    if (i < NN) g_dinv[i] = rsqrtf((float)dg);
    int v = dg - 1;
    int s = v;
#pragma unroll
    for (int off = 1; off < 32; off <<= 1) {
        int tmp = __shfl_up_sync(0xffffffffu, s, off);
        if (lane >= off) s += tmp;
    }
    if (lane == 31) warpsums[w] = s;
    __syncthreads();
    if (w == 0) {
        int ws = warpsums[lane];
#pragma unroll
        for (int off = 1; off < 32; off <<= 1) {
            int tmp = __shfl_up_sync(0xffffffffu, ws, off);
            if (lane >= off) ws += tmp;
        }
        warpsums[lane] = ws;
    }
    __syncthreads();
    int incl = s + ((w == 0) ? 0 : warpsums[w - 1]);
    int btotal = warpsums[31];

    // publish block total ASAP (flag in bit 0)
    if (t == 0) atomicExch(&g_part[b], ((unsigned)btotal << 1) | 1u);

    // parallel lookback: thread t spins on predecessor t
    if (t < b) {
        unsigned pv;
        do { pv = atomicOr(&g_part[t], 0u); } while (!(pv & 1u));
        spart[t] = pv >> 1;
    } else if (t < 128) {
        spart[t] = 0;
    }
    __syncthreads();
    if (w == 0) {
        unsigned acc = spart[lane] + spart[lane + 32] + spart[lane + 64] + spart[lane + 96];
#pragma unroll
        for (int off = 16; off > 0; off >>= 1)
            acc += __shfl_down_sync(0xffffffffu, acc, off);
        if (lane == 0) sprefix = (int)acc;
    }
    __syncthreads();
    int pref = sprefix;
    if (i < NN) {
        int o = pref + incl - v;
        g_off[i] = o;
        g_cur[i] = o;
    }
    if (b == SB - 1 && t == 1023) g_off[NN] = pref + incl;

    // --- phase B: scale this block's own y2 rows by dinv (no cross-block dep) --
    {
        size_t base = (size_t)b * 32768;     // 1024 nodes * 32 lanes
#pragma unroll
        for (int r = 0; r < 32; r++) {
            size_t idx = base + (size_t)r * 1024 + t;
            if (idx < (size_t)NN * 32) {
                float dv = g_dinv[idx >> 5];
                g_y2[idx] = mul2(g_y2[idx], pack2(dv, dv));
            }
        }
    }

    // --- phase C: grid barrier (all 98 blocks co-resident by construction) ----
    __threadfence();
    __syncthreads();
    if (t == 0) {
        atomicAdd(&g_done, 1);
        while (atomicAdd(&g_done, 0) < SB) { }
    }
    __syncthreads();

    // --- phase D: CSR scatter, grid-strided -----------------------------------
    for (int e = b * 1024 + t; e < EE; e += SB * 1024) {
        int s2 = g_src32[e], d2 = g_dst32[e];
        int pos = atomicAdd(&g_cur[d2], 1);
        g_srcs[pos] = s2;
    }
}

// ---------------- aggregate + GRU gates: warp per node (R5-proven) ------------
__global__ void k_agg() {
    int warp = (blockIdx.x * blockDim.x + threadIdx.x) >> 5;
    int lane = threadIdx.x & 31;
    if (warp >= NN) return;
    int n = warp;
    ull a0 = g_y2[(size_t)n * 32 + lane];    // self term (ys[n])
    ull a1 = 0;
    int beg = g_off[n], end = g_off[n + 1];
    int idx = beg;
    for (; idx + 1 < end; idx += 2) {
        int s0 = g_srcs[idx], s1 = g_srcs[idx + 1];
        a0 = add2(a0, g_y2[(size_t)s0 * 32 + lane]);
        a1 = add2(a1, g_y2[(size_t)s1 * 32 + lane]);
    }
    if (idx < end) a0 = add2(a0, g_y2[(size_t)g_srcs[idx] * 32 + lane]);
    float dn = g_dinv[n];
    ull acc = fma2(add2(a0, a1), pack2(dn, dn), g_beff2[lane]);
    float vz, vh;
    unpack2(acc, vz, vh);
    float z  = 1.f / (1.f + __expf(-vz));
    float ht = tanhf(vh);
    g_H[(size_t)n * HID + lane] = (1.f - z) * ht;
}

// ---------------- edge MLP: 2 edges per thread, f32x2 (R5-proven) -------------
__global__ void k_edge(const float* __restrict__ w1, const float* __restrict__ b1,
                       const float* __restrict__ w2, const float* __restrict__ b2,
                       float* __restrict__ out) {
    __shared__ ull sw1[HID * 16];       // row j: 16 packed (w1[2p][j], w1[2p+1][j])
    __shared__ float sb1[HID], sw2[HID];
    __shared__ float sb2;
    int tid = threadIdx.x;
    for (int i = tid; i < HID * 16; i += blockDim.x) {
        int j = i >> 4, p = i & 15;
        sw1[j * 16 + p] = pack2(w1[(2 * p) * HID + j], w1[(2 * p + 1) * HID + j]);
    }
    if (tid < HID) { sb1[tid] = b1[tid]; sw2[tid] = w2[tid]; }
    if (tid == 0) sb2 = b2[0];
    __syncthreads();
    int e0 = blockIdx.x * 512 + tid;
    int e1 = e0 + 256;
    bool v0 = (e0 < EE), v1 = (e1 < EE);

    ull emb0[16], emb1[16];
    if (v0) {
        const float4* Hs = (const float4*)(g_H + (size_t)g_src32[e0] * HID);
        const float4* Hd = (const float4*)(g_H + (size_t)g_dst32[e0] * HID);
#pragma unroll
        for (int i = 0; i < 8; i++) {
            float4 a = Hs[i], b = Hd[i];
            const ull* ap = (const ull*)&a; const ull* bp = (const ull*)&b;
            emb0[2 * i]     = mul2(ap[0], bp[0]);
            emb0[2 * i + 1] = mul2(ap[1], bp[1]);
        }
    }
    if (v1) {
        const float4* Hs = (const float4*)(g_H + (size_t)g_src32[e1] * HID);
        const float4* Hd = (const float4*)(g_H + (size_t)g_dst32[e1] * HID);
#pragma unroll
        for (int i = 0; i < 8; i++) {
            float4 a = Hs[i], b = Hd[i];
            const ull* ap = (const ull*)&a; const ull* bp = (const ull*)&b;
            emb1[2 * i]     = mul2(ap[0], bp[0]);
            emb1[2 * i + 1] = mul2(ap[1], bp[1]);
        }
    }
    if (!v0) return;

    float logit0 = sb2, logit1 = sb2;
#pragma unroll 2
    for (int j = 0; j < HID; j++) {
        ull acc0 = 0, acc1 = 0;
        const ull* wr = &sw1[j * 16];
#pragma unroll
        for (int p = 0; p < 16; p++) {
            ull w = wr[p];
            acc0 = fma2(emb0[p], w, acc0);
            acc1 = fma2(emb1[p], w, acc1);
        }
        float lo, hi, l1, h1v;
        unpack2(acc0, lo, hi);
        unpack2(acc1, l1, h1v);
        float h0 = fmaxf(lo + hi + sb1[j], 0.f);
        float h1 = fmaxf(l1 + h1v + sb1[j], 0.f);
        logit0 = fmaf(h0, sw2[j], logit0);
        logit1 = fmaf(h1, sw2[j], logit1);
    }
    out[e0] = 1.f / (1.f + __expf(-logit0));
    if (v1) out[e1] = 1.f / (1.f + __expf(-logit1));
}

// ---------------- launch ------------------------------------------------------
extern "C" void kernel_launch(void* const* d_in, const int* in_sizes, int n_in,
                              void* d_out, int out_size) {
    const float* x   = (const float*)d_in[0];
    const void*  ei  = d_in[1];
    const float* Wz  = (const float*)d_in[2];
    const float* bz  = (const float*)d_in[3];
    const float* Wh  = (const float*)d_in[6];
    const float* bh  = (const float*)d_in[7];
    const float* Lzw = (const float*)d_in[8];
    const float* Lzb = (const float*)d_in[9];
    const float* Lhw = (const float*)d_in[12];
    const float* Lhb = (const float*)d_in[13];
    const float* w1  = (const float*)d_in[14];
    const float* b1  = (const float*)d_in[15];
    const float* w2  = (const float*)d_in[16];
    const float* b2  = (const float*)d_in[17];
    float* out = (float*)d_out;

    k_prep<<<424, 256>>>(ei, Wz, Wh, Lzw, Lhw, bz, bh, Lzb, Lhb);
    k_main1<<<GEMMB + DEGB, 256>>>(x, ei);
    k_scanscat<<<SB, 1024>>>();
    k_agg<<<(NN * 32 + 255) / 256, 256>>>();
    k_edge<<<(EE + 511) / 512, 256>>>(w1, b1, w2, b2, out);
}

// round 8
// speedup vs baseline: 1.0407x; 1.0407x over previous
#include <cuda_runtime.h>
#include <math.h>

#define NN 100000
#define EE 1600000
#define DD 128
#define HID 32

typedef unsigned long long ull;

// ---------------- scratch (device globals) ------------------------------------
__device__ int   g_is64;
__device__ int   g_deg[NN];
__device__ float g_dinv[NN];
__device__ int   g_off[NN + 1];
__device__ int   g_cur[NN];
__device__ int   g_src32[EE];
__device__ int   g_dst32[EE];
__device__ int   g_srcs[EE];                // CSR: prescaled src element offsets (s*32)
__device__ ull   g_y2[(size_t)NN * 32];     // (z,h) packed per (node,lane); scaled by dinv
__device__ float g_H[(size_t)NN * HID];
__device__ float g_WT[64 * DD];             // WeffT[j][k], j: 0..31=z, 32..63=h
__device__ ull   g_beff2[32];               // packed (bz_eff, bh_eff)
__device__ int   g_bsum[128];
__device__ int   g_bscan[128];

// ---------------- f32x2 helpers -----------------------------------------------
__device__ __forceinline__ ull pack2(float a, float b) {
    ull r; asm("mov.b64 %0, {%1, %2};" : "=l"(r) : "f"(a), "f"(b)); return r;
}
__device__ __forceinline__ void unpack2(ull v, float& a, float& b) {
    asm("mov.b64 {%0, %1}, %2;" : "=f"(a), "=f"(b) : "l"(v));
}
__device__ __forceinline__ ull fma2(ull a, ull b, ull c) {
    ull d; asm("fma.rn.f32x2 %0, %1, %2, %3;" : "=l"(d) : "l"(a), "l"(b), "l"(c)); return d;
}
__device__ __forceinline__ ull mul2(ull a, ull b) {
    ull d; asm("mul.rn.f32x2 %0, %1, %2;" : "=l"(d) : "l"(a), "l"(b)); return d;
}
__device__ __forceinline__ ull add2(ull a, ull b) {
    ull d; asm("add.rn.f32x2 %0, %1, %2;" : "=l"(d) : "l"(a), "l"(b)); return d;
}

__device__ __forceinline__ int edge_at(const void* ei, int is64, long long idx) {
    return is64 ? (int)((const long long*)ei)[idx] : ((const int*)ei)[idx];
}

// ---------------- prep: detect + deg init + Weff^T + beff ---------------------
__global__ void k_prep(const void* ei,
                       const float* Wz, const float* Wh,
                       const float* Lzw, const float* Lhw,
                       const float* bz, const float* bh,
                       const float* Lzb, const float* Lhb) {
    int b = blockIdx.x, t = threadIdx.x;
    if (b < 391) {
        int i = b * 256 + t;
        if (i < NN) g_deg[i] = 1;           // self loop
    } else if (b == 391) {
        __shared__ int s;
        if (t == 0) s = 1;
        __syncthreads();
        const long long* p = (const long long*)ei;
        for (int i = t; i < 4096; i += 256)
            if ((p[i] >> 32) != 0) s = 0;
        __syncthreads();
        if (t == 0) g_is64 = s;
    } else {
        int idx = (b - 392) * 256 + t;      // [0, 8192)
        int k = idx >> 6, j = idx & 63;
        float acc = 0.f;
        if (j < HID) {
            for (int m = 0; m < HID; m++) acc = fmaf(Wz[k * HID + m], Lzw[m * HID + j], acc);
        } else {
            int jj = j - HID;
            for (int m = 0; m < HID; m++) acc = fmaf(Wh[k * HID + m], Lhw[m * HID + jj], acc);
        }
        g_WT[j * DD + k] = acc;             // transposed store
        if (b == 392 && t < 32) {
            float az = Lzb[t], ah = Lhb[t];
            for (int m = 0; m < HID; m++) {
                az = fmaf(bz[m], Lzw[m * HID + t], az);
                ah = fmaf(bh[m], Lhw[m * HID + t], ah);
            }
            g_beff2[t] = pack2(az, ah);
        }
    }
}

// ---------------- fused: GEMM (blocks [0,GEMMB)) + edge conv/degree ----------
#define GEMMB 3125
#define DEGB  6250
__global__ void k_main1(const float* __restrict__ x, const void* __restrict__ ei) {
    __shared__ float sWT[64 * 130];         // padded rows: stride 130 floats
    int t = threadIdx.x;
    if (blockIdx.x < GEMMB) {
        for (int i = t; i < 64 * 128; i += 256) {
            int j = i >> 7, k = i & 127;
            sWT[j * 130 + k] = g_WT[i];
        }
        __syncthreads();
        int warp = t >> 5, lane = t & 31;
        int n0 = (blockIdx.x * 8 + warp) * 4;       // 4 nodes per warp
        if (n0 >= NN) return;
        const float4* x4 = (const float4*)x;
        ull az[4] = {0, 0, 0, 0}, ah[4] = {0, 0, 0, 0};
        const ull* wzr = (const ull*)&sWT[lane * 130];
        const ull* whr = (const ull*)&sWT[(lane + 32) * 130];
#pragma unroll 4
        for (int k4 = 0; k4 < 32; k4++) {
            float4 a0 = x4[(size_t)(n0 + 0) * 32 + k4];
            float4 a1 = x4[(size_t)(n0 + 1) * 32 + k4];
            float4 a2 = x4[(size_t)(n0 + 2) * 32 + k4];
            float4 a3 = x4[(size_t)(n0 + 3) * 32 + k4];
            ull wz0 = wzr[k4 * 2], wz1 = wzr[k4 * 2 + 1];
            ull wh0 = whr[k4 * 2], wh1 = whr[k4 * 2 + 1];
            const ull* p0 = (const ull*)&a0; const ull* p1 = (const ull*)&a1;
            const ull* p2 = (const ull*)&a2; const ull* p3 = (const ull*)&a3;
            az[0] = fma2(p0[0], wz0, az[0]); az[0] = fma2(p0[1], wz1, az[0]);
            ah[0] = fma2(p0[0], wh0, ah[0]); ah[0] = fma2(p0[1], wh1, ah[0]);
            az[1] = fma2(p1[0], wz0, az[1]); az[1] = fma2(p1[1], wz1, az[1]);
            ah[1] = fma2(p1[0], wh0, ah[1]); ah[1] = fma2(p1[1], wh1, ah[1]);
            az[2] = fma2(p2[0], wz0, az[2]); az[2] = fma2(p2[1], wz1, az[2]);
            ah[2] = fma2(p2[0], wh0, ah[2]); ah[2] = fma2(p2[1], wh1, ah[2]);
            az[3] = fma2(p3[0], wz0, az[3]); az[3] = fma2(p3[1], wz1, az[3]);
            ah[3] = fma2(p3[0], wh0, ah[3]); ah[3] = fma2(p3[1], wh1, ah[3]);
        }
#pragma unroll
        for (int i = 0; i < 4; i++) {
            float zl, zh, hl, hh;
            unpack2(az[i], zl, zh);
            unpack2(ah[i], hl, hh);
            g_y2[(size_t)(n0 + i) * 32 + lane] = pack2(zl + zh, hl + hh);
        }
    } else {
        int is64 = g_is64;
        int e = (blockIdx.x - GEMMB) * 256 + t;
        if (e < EE) {
            int s = edge_at(ei, is64, e);
            int d = edge_at(ei, is64, (long long)EE + e);
            g_src32[e] = s;
            g_dst32[e] = d;
            atomicAdd(&g_deg[d], 1);
        }
    }
}

// ---------------- 3-phase scan (exclusive scan of deg-1) + dinv ---------------
__global__ void k_scan1() {
    __shared__ int warpsums[32];
    int t = threadIdx.x, lane = t & 31, w = t >> 5;
    int i = blockIdx.x * 1024 + t;
    int dg = (i < NN) ? g_deg[i] : 1;
    if (i < NN) g_dinv[i] = rsqrtf((float)dg);
    int v = dg - 1;
    int s = v;
#pragma unroll
    for (int off = 1; off < 32; off <<= 1) {
        int tmp = __shfl_up_sync(0xffffffffu, s, off);
        if (lane >= off) s += tmp;
    }
    if (lane == 31) warpsums[w] = s;
    __syncthreads();
    if (w == 0) {
        int ws = warpsums[lane];
#pragma unroll
        for (int off = 1; off < 32; off <<= 1) {
            int tmp = __shfl_up_sync(0xffffffffu, ws, off);
            if (lane >= off) ws += tmp;
        }
        warpsums[lane] = ws;
    }
    __syncthreads();
    int incl = s + ((w == 0) ? 0 : warpsums[w - 1]);
    if (i < NN) g_off[i] = incl - v;        // block-local exclusive
    if (t == 1023) g_bsum[blockIdx.x] = incl;
}

__global__ void k_scan2() {
    __shared__ int sh[128];
    int t = threadIdx.x;
    int v = (t < 98) ? g_bsum[t] : 0;
    sh[t] = v;
    __syncthreads();
    for (int off = 1; off < 128; off <<= 1) {
        int tmp = (t >= off) ? sh[t - off] : 0;
        __syncthreads();
        sh[t] += tmp;
        __syncthreads();
    }
    if (t < 98) g_bscan[t] = sh[t] - v;
    if (t == 97) g_off[NN] = sh[97];
}

__global__ void k_scan3() {
    int i = blockIdx.x * 1024 + threadIdx.x;
    if (i < NN) {
        int o = g_off[i] + g_bscan[blockIdx.x];
        g_off[i] = o;
        g_cur[i] = o;
    }
}

// ---------------- CSR scatter (blocks [0,SCATB)) + y2 *= dinv (rest) ---------
#define SCATB 6250
#define SCALB 3125          // 3125*256*4 = 3.2M ull = NN*32
__global__ void k_scatter() {
    int b = blockIdx.x, t = threadIdx.x;
    if (b < SCATB) {
        int e = b * 256 + t;
        if (e < EE) {
            int s = g_src32[e], d = g_dst32[e];
            int pos = atomicAdd(&g_cur[d], 1);
            g_srcs[pos] = s * 32;           // prescaled element offset into g_y2
        }
    } else {
        size_t base = (size_t)(b - SCATB) * 1024 + t;
#pragma unroll
        for (int r = 0; r < 4; r++) {
            size_t i = base + (size_t)r * 256;
            if (i < (size_t)NN * 32) {
                float dv = g_dinv[i >> 5];
                g_y2[i] = mul2(g_y2[i], pack2(dv, dv));
            }
        }
    }
}

// ---------------- aggregate + GRU gates: warp per node ------------------------
__global__ void k_agg() {
    int warp = (blockIdx.x * blockDim.x + threadIdx.x) >> 5;
    int lane = threadIdx.x & 31;
    if (warp >= NN) return;
    int n = warp;
    ull a0 = g_y2[(size_t)n * 32 + lane];    // self term (ys[n])
    ull a1 = 0;
    int beg = g_off[n], end = g_off[n + 1];
    int idx = beg;
    for (; idx + 1 < end; idx += 2) {
        int o0 = g_srcs[idx] + lane;         // prescaled: pure IADD addressing
        int o1 = g_srcs[idx + 1] + lane;
        a0 = add2(a0, g_y2[o0]);
        a1 = add2(a1, g_y2[o1]);
    }
    if (idx < end) a0 = add2(a0, g_y2[g_srcs[idx] + lane]);
    float dn = g_dinv[n];
    ull acc = fma2(add2(a0, a1), pack2(dn, dn), g_beff2[lane]);
    float vz, vh;
    unpack2(acc, vz, vh);
    float z  = 1.f / (1.f + __expf(-vz));
    float ht = tanhf(vh);
    g_H[(size_t)n * HID + lane] = (1.f - z) * ht;
}

// ---------------- edge MLP: 2 edges per thread, f32x2 (R5-proven) -------------
__global__ void k_edge(const float* __restrict__ w1, const float* __restrict__ b1,
                       const float* __restrict__ w2, const float* __restrict__ b2,
                       float* __restrict__ out) {
    __shared__ ull sw1[HID * 16];       // row j: 16 packed (w1[2p][j], w1[2p+1][j])
    __shared__ float sb1[HID], sw2[HID];
    __shared__ float sb2;
    int tid = threadIdx.x;
    for (int i = tid; i < HID * 16; i += blockDim.x) {
        int j = i >> 4, p = i & 15;
        sw1[j * 16 + p] = pack2(w1[(2 * p) * HID + j], w1[(2 * p + 1) * HID + j]);
    }
    if (tid < HID) { sb1[tid] = b1[tid]; sw2[tid] = w2[tid]; }
    if (tid == 0) sb2 = b2[0];
    __syncthreads();
    int e0 = blockIdx.x * 512 + tid;
    int e1 = e0 + 256;
    bool v0 = (e0 < EE), v1 = (e1 < EE);

    ull emb0[16], emb1[16];
    if (v0) {
        const float4* Hs = (const float4*)(g_H + (size_t)g_src32[e0] * HID);
        const float4* Hd = (const float4*)(g_H + (size_t)g_dst32[e0] * HID);
#pragma unroll
        for (int i = 0; i < 8; i++) {
            float4 a = Hs[i], b = Hd[i];
            const ull* ap = (const ull*)&a; const ull* bp = (const ull*)&b;
            emb0[2 * i]     = mul2(ap[0], bp[0]);
            emb0[2 * i + 1] = mul2(ap[1], bp[1]);
        }
    }
    if (v1) {
        const float4* Hs = (const float4*)(g_H + (size_t)g_src32[e1] * HID);
        const float4* Hd = (const float4*)(g_H + (size_t)g_dst32[e1] * HID);
#pragma unroll
        for (int i = 0; i < 8; i++) {
            float4 a = Hs[i], b = Hd[i];
            const ull* ap = (const ull*)&a; const ull* bp = (const ull*)&b;
            emb1[2 * i]     = mul2(ap[0], bp[0]);
            emb1[2 * i + 1] = mul2(ap[1], bp[1]);
        }
    }
    if (!v0) return;

    float logit0 = sb2, logit1 = sb2;
#pragma unroll 2
    for (int j = 0; j < HID; j++) {
        ull acc0 = 0, acc1 = 0;
        const ull* wr = &sw1[j * 16];
#pragma unroll
        for (int p = 0; p < 16; p++) {
            ull w = wr[p];
            acc0 = fma2(emb0[p], w, acc0);
            acc1 = fma2(emb1[p], w, acc1);
        }
        float lo, hi, l1, h1v;
        unpack2(acc0, lo, hi);
        unpack2(acc1, l1, h1v);
        float h0 = fmaxf(lo + hi + sb1[j], 0.f);
        float h1 = fmaxf(l1 + h1v + sb1[j], 0.f);
        logit0 = fmaf(h0, sw2[j], logit0);
        logit1 = fmaf(h1, sw2[j], logit1);
    }
    out[e0] = 1.f / (1.f + __expf(-logit0));
    if (v1) out[e1] = 1.f / (1.f + __expf(-logit1));
}

// ---------------- launch ------------------------------------------------------
extern "C" void kernel_launch(void* const* d_in, const int* in_sizes, int n_in,
                              void* d_out, int out_size) {
    const float* x   = (const float*)d_in[0];
    const void*  ei  = d_in[1];
    const float* Wz  = (const float*)d_in[2];
    const float* bz  = (const float*)d_in[3];
    const float* Wh  = (const float*)d_in[6];
    const float* bh  = (const float*)d_in[7];
    const float* Lzw = (const float*)d_in[8];
    const float* Lzb = (const float*)d_in[9];
    const float* Lhw = (const float*)d_in[12];
    const float* Lhb = (const float*)d_in[13];
    const float* w1  = (const float*)d_in[14];
    const float* b1  = (const float*)d_in[15];
    const float* w2  = (const float*)d_in[16];
    const float* b2  = (const float*)d_in[17];
    float* out = (float*)d_out;

    k_prep<<<424, 256>>>(ei, Wz, Wh, Lzw, Lhw, bz, bh, Lzb, Lhb);
    k_main1<<<GEMMB + DEGB, 256>>>(x, ei);
    k_scan1<<<98, 1024>>>();
    k_scan2<<<1, 128>>>();
    k_scan3<<<98, 1024>>>();
    k_scatter<<<SCATB + SCALB, 256>>>();
    k_agg<<<(NN * 32 + 255) / 256, 256>>>();
    k_edge<<<(EE + 511) / 512, 256>>>(w1, b1, w2, b2, out);
}